// round 9
// baseline (speedup 1.0000x reference)
#include <cuda_runtime.h>

#define N_NODES 10000
#define N_EDGES 320000
#define QUADS (N_EDGES / 4)
#define NB 148
#define NT 1024
#define NTHR (NB * NT)
#define BM_WORDS 320
#define DC 68   // dot chunk: 148 blocks x 68 >= 10000

// INVARIANT: all __device__ scratch that is accumulated into (CL*, bm*, D,
// sig) is ZERO at kernel entry and restored to ZERO before exit. g_W12/g_v2
// are fully overwritten each call before use. L1-cached __ldg of
// atomically-written arrays is safe: L1 is flushed at launch boundaries and
// each array is never regular-loaded before its producer phase completes.
__device__ float2 g_CL1[N_NODES];   // {R1, R2}
__device__ float4 g_CL2[N_NODES];   // {R3, R5, R4, R6}
__device__ float4 g_CL3a[N_NODES];  // {R7, R10, R11, pad}
__device__ float4 g_CL3b[N_NODES];  // {R8, R9, R12, pad}
__device__ float4 g_CL4[N_NODES];   // {R13, R15, R14, R16}
__device__ unsigned g_bm1[BM_WORDS];
__device__ unsigned g_bm2[BM_WORDS];
__device__ float g_D[17][4][64];
__device__ float g_W12[36][64][128]; // W1[pc1] @ W2[pc2], t = pc2*6+pc1
__device__ float g_v2[6][128];       // b1 @ W2[pc2]
__device__ float g_sig[5];
__device__ int g_count;             // returns to 0 at each barrier
__device__ volatile int g_gen;      // monotonic; equality-compare only

__constant__ int c_VEC_ID[5][5] = {
    {0, 1, 3, 2, 6},
    {1, 3, 7, 4, 9},
    {3, 7, 13, 8, 14},
    {2, 5, 10, 6, 12},
    {6, 11, 15, 12, 16}};
__constant__ int c_SVA[12] = {1, 2, 3, 5, 4, 6, 7, 10, 11, 8, 9, 12};
__constant__ int c_SVB[4] = {13, 15, 14, 16};

__device__ __forceinline__ void red2(float* p, float a, float b) {
    asm volatile("red.global.add.v2.f32 [%0], {%1,%2};" :: "l"(p), "f"(a), "f"(b) : "memory");
}
__device__ __forceinline__ void red4(float* p, float a, float b, float c, float d) {
    asm volatile("red.global.add.v4.f32 [%0], {%1,%2,%3,%4};"
                 :: "l"(p), "f"(a), "f"(b), "f"(c), "f"(d) : "memory");
}

__device__ __forceinline__ void barrier_arrive(int target) {
    __syncthreads();
    if (threadIdx.x == 0) {
        __threadfence();
        int gen = g_gen;
        if (atomicAdd(&g_count, 1) == target - 1) {
            g_count = 0;
            __threadfence();
            g_gen = gen + 1;
        }
    }
}
__device__ __forceinline__ void barrier_wait(int target) {
    __syncthreads();
    if (threadIdx.x == 0) {
        __threadfence();
        int gen = g_gen;
        if (atomicAdd(&g_count, 1) == target - 1) {
            g_count = 0;
            __threadfence();
            g_gen = gen + 1;
        } else {
            while (g_gen == gen) __nanosleep(64);
        }
    }
    __syncthreads();
}

__global__ void __launch_bounds__(NT, 1)
fused_kernel(const int* __restrict__ eidx, const float* __restrict__ evals,
             const float* __restrict__ x,
             const float* __restrict__ W1, const float* __restrict__ b1,
             const float* __restrict__ W2, const float* __restrict__ b2,
             float* __restrict__ out) {
    __shared__ __align__(16) float pool[1024];
    __shared__ unsigned sbm[BM_WORDS];

    const int tid = threadIdx.x;
    const int blk = blockIdx.x;
    const int gtid = blk * NT + tid;
    const float4 z4 = make_float4(0.f, 0.f, 0.f, 0.f);

    // ---- P1: blocks 0..111 lvl1 (parent = e_0) + bm1; blocks 112..147 W12/v2 ----
    if (blk < 112) {
        for (int q = blk * NT + tid; q < 2 * QUADS; q += 112 * NT) {
            int g = q >= QUADS;
            int j = q - g * QUADS;
            const int* eb = eidx + (size_t)g * 2 * N_EDGES;
            int4 r = __ldg((const int4*)eb + j);
            if (r.x == 0 || r.y == 0 || r.z == 0 || r.w == 0) {
                const int ri[4] = {r.x, r.y, r.z, r.w};
                float* base = (float*)g_CL1 + g;
#pragma unroll
                for (int i = 0; i < 4; i++)
                    if (ri[i] == 0) {
                        int c = __ldg(eb + N_EDGES + j * 4 + i);
                        float v = __ldg(evals + (size_t)g * N_EDGES + j * 4 + i);
                        atomicAdd(base + c * 2, v);
                        atomicOr(&g_bm1[c >> 5], 1u << (c & 31));
                    }
            }
        }
    } else {
        // W12[t][f][g] = sum_h W1[pc1][f][h] * W2[pc2][h][g]; t = pc2*6+pc1
        int t = blk - 112;
        int pc1 = t % 6, pc2 = t / 6;
        const float* W1p = W1 + (size_t)pc1 * 64 * 128;
        const float* W2p = W2 + (size_t)pc2 * 128 * 128;
        int g = tid & 127, fo = tid >> 7;  // 8 f-groups of 8
        float acc[8];
#pragma unroll
        for (int i = 0; i < 8; i++) acc[i] = 0.f;
        float accB = 0.f;
        for (int h = 0; h < 128; h++) {
            float w2 = __ldg(W2p + (size_t)h * 128 + g);
#pragma unroll
            for (int i = 0; i < 8; i++)
                acc[i] += __ldg(W1p + (size_t)(fo * 8 + i) * 128 + h) * w2;
            accB += __ldg(b1 + h) * w2;  // used only by (pc1==0, fo==0)
        }
        float* Wout = &g_W12[t][0][0];
#pragma unroll
        for (int i = 0; i < 8; i++)
            Wout[(size_t)(fo * 8 + i) * 128 + g] = acc[i];
        if (pc1 == 0 && fo == 0) g_v2[pc2][g] = accB;
    }
    barrier_wait(NB);

    // ---- P2: lvl2 (bm1-filtered, L1 gathers) + build bm2 ----
    if (tid < BM_WORDS) sbm[tid] = __ldg(&g_bm1[tid]);
    __syncthreads();
    for (int q = gtid; q < 2 * QUADS; q += NTHR) {
        int g = q >= QUADS;
        int j = q - g * QUADS;
        const int* eb = eidx + (size_t)g * 2 * N_EDGES;
        int4 r = __ldg((const int4*)eb + j);
        const int ri[4] = {r.x, r.y, r.z, r.w};
        unsigned any = 0;
#pragma unroll
        for (int i = 0; i < 4; i++)
            any |= (sbm[ri[i] >> 5] >> (ri[i] & 31)) & 1u ? (1u << i) : 0u;
        if (!any) continue;
        float* base = (float*)g_CL2 + 2 * g;
#pragma unroll
        for (int i = 0; i < 4; i++)
            if (any & (1u << i)) {
                float2 qv = __ldg(g_CL1 + ri[i]);
                if ((qv.x != 0.f) | (qv.y != 0.f)) {
                    int c = __ldg(eb + N_EDGES + j * 4 + i);
                    float v = __ldg(evals + (size_t)g * N_EDGES + j * 4 + i);
                    red2(base + c * 4, v * qv.x, v * qv.y);
                    atomicOr(&g_bm2[c >> 5], 1u << (c & 31));
                }
            }
    }
    barrier_wait(NB);

    // ---- P3: lvl3 (bm2-filtered, L1 gathers) ----
    if (tid < BM_WORDS) sbm[tid] = __ldg(&g_bm2[tid]);
    __syncthreads();
    for (int q = gtid; q < 2 * QUADS; q += NTHR) {
        int g = q >= QUADS;
        int j = q - g * QUADS;
        const int* eb = eidx + (size_t)g * 2 * N_EDGES;
        int4 r = __ldg((const int4*)eb + j);
        const int ri[4] = {r.x, r.y, r.z, r.w};
        unsigned any = 0;
#pragma unroll
        for (int i = 0; i < 4; i++)
            any |= (sbm[ri[i] >> 5] >> (ri[i] & 31)) & 1u ? (1u << i) : 0u;
        if (!any) continue;
        float4* dst = g ? g_CL3b : g_CL3a;
#pragma unroll
        for (int i = 0; i < 4; i++)
            if (any & (1u << i)) {
                float4 qv = __ldg(g_CL2 + ri[i]);
                float p0 = qv.x;
                float p1 = g ? qv.z : qv.y;
                float p2 = qv.w;
                if ((p0 != 0.f) | (p1 != 0.f) | (p2 != 0.f)) {
                    int c = __ldg(eb + N_EDGES + j * 4 + i);
                    float v = __ldg(evals + (size_t)g * N_EDGES + j * 4 + i);
                    red4((float*)&dst[c], v * p0, v * p1, v * p2, 0.f);
                }
            }
    }
    barrier_wait(NB);

    // ---- P4: lvl4 scan, then in-phase dot of 12 final slots + sigma + zeroing ----
    for (int q = gtid; q < 2 * QUADS; q += NTHR) {
        int g = q >= QUADS;
        int j = q - g * QUADS;
        const int* eb = eidx + (size_t)g * 2 * N_EDGES;
        const float4* src = g ? g_CL3b : g_CL3a;
        int4 r = __ldg((const int4*)eb + j);
        int4 c = __ldg((const int4*)(eb + N_EDGES) + j);
        float4 v = __ldg((const float4*)(evals + (size_t)g * N_EDGES) + j);
        float* base = (float*)g_CL4 + 2 * g;
        {
            float4 q0 = __ldg(src + r.x), q1 = __ldg(src + r.y);
            if ((q0.x != 0.f) | (q0.z != 0.f)) red2(base + c.x * 4, v.x * q0.x, v.x * q0.z);
            if ((q1.x != 0.f) | (q1.z != 0.f)) red2(base + c.y * 4, v.y * q1.x, v.y * q1.z);
        }
        {
            float4 q2 = __ldg(src + r.z), q3 = __ldg(src + r.w);
            if ((q2.x != 0.f) | (q2.z != 0.f)) red2(base + c.z * 4, v.z * q2.x, v.z * q2.z);
            if ((q3.x != 0.f) | (q3.z != 0.f)) red2(base + c.w * 4, v.w * q3.x, v.w * q3.z);
        }
    }
    // P5a (CL1/CL2/CL3 are final since P3; read-only wrt concurrent lvl4 scan)
    {
        int n0 = blk * DC;
        int lim = min(DC, N_NODES - n0);
        for (int i = tid; i < lim; i += NT) {
            int gn = n0 + i;
            float2 a = __ldg(g_CL1 + gn);
            float4 c2 = __ldg(g_CL2 + gn);
            float4 c3a = __ldg(g_CL3a + gn);
            float4 c3b = __ldg(g_CL3b + gn);
            pool[0 * DC + i] = a.x;   pool[1 * DC + i] = a.y;
            pool[2 * DC + i] = c2.x;  pool[3 * DC + i] = c2.y;
            pool[4 * DC + i] = c2.z;  pool[5 * DC + i] = c2.w;
            pool[6 * DC + i] = c3a.x; pool[7 * DC + i] = c3a.y;
            pool[8 * DC + i] = c3a.z;
            pool[9 * DC + i] = c3b.x; pool[10 * DC + i] = c3b.y;
            pool[11 * DC + i] = c3b.z;
            g_CL1[gn] = make_float2(0.f, 0.f);  // after loads; program order
            g_CL2[gn] = z4;
        }
        if (blk == 0 && tid >= 512 && tid < 512 + BM_WORDS) {
            g_bm1[tid - 512] = 0u;
            g_bm2[tid - 512] = 0u;
        }
        __syncthreads();
        if (tid < 128) {  // sigma: sig[1..4] = column sums of slots {0,2,1,5}
            const int slots[4] = {0, 2, 1, 5};
            int vi = tid >> 5, lane = tid & 31;
            float s = 0.f;
            for (int n = lane; n < lim; n += 32) s += pool[slots[vi] * DC + n];
#pragma unroll
            for (int off = 16; off; off >>= 1) s += __shfl_down_sync(0xffffffffu, s, off);
            if (lane == 0) atomicAdd(&g_sig[vi + 1], s);
        }
        int f = tid & 63;
        int bb = (tid >> 6) & 3;
        int vg = tid >> 8;  // 0..3, 3 slots each
        float a0 = 0.f, a1 = 0.f, a2 = 0.f;
        const float* xb = x + ((size_t)bb * N_NODES + n0) * 64 + f;
        const float* rsv = pool + vg * 3 * DC;
        for (int nn = 0; nn < lim; nn++) {
            float xv = __ldg(xb + (size_t)nn * 64);
            a0 += rsv[0 * DC + nn] * xv;
            a1 += rsv[1 * DC + nn] * xv;
            a2 += rsv[2 * DC + nn] * xv;
        }
        atomicAdd(&g_D[c_SVA[vg * 3 + 0]][bb][f], a0);
        atomicAdd(&g_D[c_SVA[vg * 3 + 1]][bb][f], a1);
        atomicAdd(&g_D[c_SVA[vg * 3 + 2]][bb][f], a2);
    }
    barrier_wait(NB);

    // ---- P5b: dot(CL4) + zero CL3/CL4; blocks 144..147 also out = b2 + sigma*v2 ----
    {
        int n0 = blk * DC;
        int lim = min(DC, N_NODES - n0);
        for (int i = tid; i < lim; i += NT) {
            int gn = n0 + i;
            float4 c4 = __ldg(g_CL4 + gn);
            pool[0 * DC + i] = c4.x; pool[1 * DC + i] = c4.y;
            pool[2 * DC + i] = c4.z; pool[3 * DC + i] = c4.w;
            g_CL4[gn] = z4;
            g_CL3a[gn] = z4;
            g_CL3b[gn] = z4;
        }
        __syncthreads();
        int f = tid & 63;
        int bb = (tid >> 6) & 3;
        int vg = tid >> 8;
        float a0 = 0.f;
        const float* xb = x + ((size_t)bb * N_NODES + n0) * 64 + f;
        const float* rsv = pool + vg * DC;
        for (int nn = 0; nn < lim; nn++)
            a0 += rsv[nn] * __ldg(xb + (size_t)nn * 64);
        atomicAdd(&g_D[c_SVB[vg]][bb][f], a0);
        if (blk >= 144 && tid < 128) {
            int b = blk - 144;
            float o = __ldg(b2 + tid);
#pragma unroll
            for (int pc2 = 0; pc2 < 6; pc2++) {
                int e2 = pc2 / 3, k2 = pc2 % 3;
                int si2 = (k2 == 0) ? 0 : (e2 * 2 + k2);
                float sg = (si2 == 0) ? 1.0f : __ldg(&g_sig[si2]);
                o += sg * __ldg(&g_v2[pc2][tid]);
            }
            out[(size_t)b * 128 + tid] = o;
        }
    }
    if (blk >= 144) { barrier_arrive(NB); return; }
    barrier_wait(NB);

    // ---- P6: blocks 0..143 = (b, pair) matvec D[vid] @ W12[pair] -> out ----
    {
        int b = blk & 3, t = blk >> 2;  // t = 0..35
        int pc1 = t % 6, pc2 = t / 6;
        int e1 = pc1 / 3, k1 = pc1 % 3;
        int pi1 = (k1 == 0) ? 0 : (e1 * 2 + k1);
        int e2 = pc2 / 3, k2 = pc2 % 3;
        int si2 = (k2 == 0) ? 0 : (e2 * 2 + k2);
        int vid = c_VEC_ID[si2][pi1];
        const float* Dp = vid ? &g_D[vid][b][0] : (x + (size_t)b * N_NODES * 64);
        const float* Wp = &g_W12[t][0][0];
        int g = tid & 127, sub = tid >> 7;  // 8 subs x 8 f each
        float acc = 0.f;
#pragma unroll
        for (int i = 0; i < 8; i++) {
            int f = sub * 8 + i;
            acc += __ldg(Dp + f) * __ldg(Wp + (size_t)f * 128 + g);
        }
        pool[sub * 128 + g] = acc;
        __syncthreads();
        if (sub == 0) {
            float s = 0.f;
#pragma unroll
            for (int i = 0; i < 8; i++) s += pool[i * 128 + g];
            atomicAdd(out + (size_t)b * 128 + g, s);
        }
    }
    // ---- tail: zero D and sig after all readers are done ----
    if (blk == 0) {
        barrier_wait(144);
        for (int i = tid; i < 17 * 4 * 64; i += NT) (&g_D[0][0][0])[i] = 0.f;
        if (tid < 5) g_sig[tid] = 0.f;
    } else {
        barrier_arrive(144);
    }
}

extern "C" void kernel_launch(void* const* d_in, const int* in_sizes, int n_in,
                              void* d_out, int out_size) {
    const float* x = nullptr;
    const int* eidx = nullptr;
    const float* evals = nullptr;
    const float *W1 = nullptr, *b1 = nullptr, *W2 = nullptr, *b2 = nullptr;
    for (int i = 0; i < n_in; i++) {
        switch (in_sizes[i]) {
            case 2560000: x = (const float*)d_in[i]; break;
            case 1280000: eidx = (const int*)d_in[i]; break;
            case 640000:  evals = (const float*)d_in[i]; break;
            case 49152:   W1 = (const float*)d_in[i]; break;
            case 98304:   W2 = (const float*)d_in[i]; break;
            case 128:
                if (!b1) b1 = (const float*)d_in[i];
                else b2 = (const float*)d_in[i];
                break;
        }
    }
    float* out = (float*)d_out;
    fused_kernel<<<NB, NT>>>(eidx, evals, x, W1, b1, W2, b2, out);
}

// round 10
// speedup vs baseline: 1.4491x; 1.4491x over previous
#include <cuda_runtime.h>

#define N_NODES 10000
#define N_EDGES 320000
#define QUADS (N_EDGES / 4)
#define NB 148
#define NT 1024
#define NTHR (NB * NT)
#define BM_WORDS 320
#define DC 68   // dot chunk: 148 blocks x 68 >= 10000

// INVARIANT: accumulated scratch (CL*, bm*, D, T, sig) is ZERO at kernel entry
// and restored to ZERO before exit. g_RC is fully overwritten in P1 before any
// read. L1-cached __ldg of data written earlier in this launch is safe: L1 is
// flushed at launch boundaries, global stores/atomics don't allocate in L1,
// and no array is regular-loaded before its producer phase's barrier.
__device__ float2 g_CL1[N_NODES];   // {R1, R2}
__device__ float4 g_CL2[N_NODES];   // {R3, R5, R4, R6}
__device__ float4 g_CL3a[N_NODES];  // {R7, R11, R10, pad}  (lvl4 reads .xy)
__device__ float4 g_CL3b[N_NODES];  // {R8, R12, R9, pad}   (lvl4 reads .xy)
__device__ float4 g_CL4[N_NODES];   // {R13, R15, R14, R16}
__device__ unsigned g_RC[2][N_EDGES];  // packed (row | col<<16) per GSO
__device__ unsigned g_bm1[BM_WORDS];
__device__ unsigned g_bm2[BM_WORDS];
__device__ float g_D[17][4][64];
__device__ float g_T[5][4][128];
__device__ float g_sig[5];
__device__ int g_count;             // returns to 0 at each barrier
__device__ volatile int g_gen;      // monotonic; equality-compare only

__constant__ int c_VEC_ID[5][5] = {
    {0, 1, 3, 2, 6},
    {1, 3, 7, 4, 9},
    {3, 7, 13, 8, 14},
    {2, 5, 10, 6, 12},
    {6, 11, 15, 12, 16}};
// pool slots: CL1.xy, CL2.xyzw, CL3a.xyz, CL3b.xyz  (new CL3 slot order)
__constant__ int c_SVID[16] = {1, 2, 3, 5, 4, 6, 7, 11, 10, 8, 12, 9, 13, 15, 14, 16};

__device__ __forceinline__ void red2(float* p, float a, float b) {
    asm volatile("red.global.add.v2.f32 [%0], {%1,%2};" :: "l"(p), "f"(a), "f"(b) : "memory");
}
__device__ __forceinline__ void red4(float* p, float a, float b, float c, float d) {
    asm volatile("red.global.add.v4.f32 [%0], {%1,%2,%3,%4};"
                 :: "l"(p), "f"(a), "f"(b), "f"(c), "f"(d) : "memory");
}

__device__ __forceinline__ void barrier_arrive(int target) {
    __syncthreads();
    if (threadIdx.x == 0) {
        __threadfence();
        int gen = g_gen;
        if (atomicAdd(&g_count, 1) == target - 1) {
            g_count = 0;
            __threadfence();
            g_gen = gen + 1;
        }
    }
}
__device__ __forceinline__ void barrier_wait(int target) {
    __syncthreads();
    if (threadIdx.x == 0) {
        __threadfence();
        int gen = g_gen;
        if (atomicAdd(&g_count, 1) == target - 1) {
            g_count = 0;
            __threadfence();
            g_gen = gen + 1;
        } else {
            while (g_gen == gen) __nanosleep(64);
        }
    }
    __syncthreads();
}

__global__ void __launch_bounds__(NT, 1)
fused_kernel(const int* __restrict__ eidx, const float* __restrict__ evals,
             const float* __restrict__ x,
             const float* __restrict__ W1, const float* __restrict__ b1,
             const float* __restrict__ W2, const float* __restrict__ b2,
             float* __restrict__ out) {
    __shared__ __align__(16) float pool[1920];
    __shared__ unsigned sbm[BM_WORDS];
    float4 (*part)[32] = reinterpret_cast<float4(*)[32]>(pool);

    const int tid = threadIdx.x;
    const int blk = blockIdx.x;
    const int gtid = blk * NT + tid;
    const float4 z4 = make_float4(0.f, 0.f, 0.f, 0.f);

    // ---- P1: lvl1 (parent = e_0) + build bm1 + pack RC = row | col<<16 ----
    for (int q = gtid; q < 2 * QUADS; q += NTHR) {
        int g = q >= QUADS;
        int j = q - g * QUADS;
        const int* eb = eidx + (size_t)g * 2 * N_EDGES;
        int4 r = __ldg((const int4*)eb + j);
        int4 c = __ldg((const int4*)(eb + N_EDGES) + j);
        uint4 p;
        p.x = (unsigned)r.x | ((unsigned)c.x << 16);
        p.y = (unsigned)r.y | ((unsigned)c.y << 16);
        p.z = (unsigned)r.z | ((unsigned)c.z << 16);
        p.w = (unsigned)r.w | ((unsigned)c.w << 16);
        ((uint4*)g_RC[g])[j] = p;
        if (r.x == 0 || r.y == 0 || r.z == 0 || r.w == 0) {
            const int ri[4] = {r.x, r.y, r.z, r.w};
            const int ci[4] = {c.x, c.y, c.z, c.w};
            float* base = (float*)g_CL1 + g;
#pragma unroll
            for (int i = 0; i < 4; i++)
                if (ri[i] == 0) {
                    float v = __ldg(evals + (size_t)g * N_EDGES + j * 4 + i);
                    atomicAdd(base + ci[i] * 2, v);
                    atomicOr(&g_bm1[ci[i] >> 5], 1u << (ci[i] & 31));
                }
        }
    }
    barrier_wait(NB);

    // ---- P2: lvl2 (bm1-filtered; RC stream) + build bm2 ----
    if (tid < BM_WORDS) sbm[tid] = __ldg(&g_bm1[tid]);
    __syncthreads();
    for (int q = gtid; q < 2 * QUADS; q += NTHR) {
        int g = q >= QUADS;
        int j = q - g * QUADS;
        uint4 rc = __ldg((const uint4*)g_RC[g] + j);
        const unsigned pk[4] = {rc.x, rc.y, rc.z, rc.w};
        unsigned any = 0;
#pragma unroll
        for (int i = 0; i < 4; i++) {
            unsigned rr = pk[i] & 0xffffu;
            any |= (sbm[rr >> 5] >> (rr & 31)) & 1u ? (1u << i) : 0u;
        }
        if (!any) continue;
        float* base = (float*)g_CL2 + 2 * g;
#pragma unroll
        for (int i = 0; i < 4; i++)
            if (any & (1u << i)) {
                float2 qv = __ldg(g_CL1 + (pk[i] & 0xffffu));
                if ((qv.x != 0.f) | (qv.y != 0.f)) {
                    unsigned cc = pk[i] >> 16;
                    float v = __ldg(evals + (size_t)g * N_EDGES + j * 4 + i);
                    red2(base + cc * 4, v * qv.x, v * qv.y);
                    atomicOr(&g_bm2[cc >> 5], 1u << (cc & 31));
                }
            }
    }
    barrier_wait(NB);

    // ---- P3: lvl3 (bm2-filtered; RC stream, vector vals) ----
    if (tid < BM_WORDS) sbm[tid] = __ldg(&g_bm2[tid]);
    __syncthreads();
    for (int q = gtid; q < 2 * QUADS; q += NTHR) {
        int g = q >= QUADS;
        int j = q - g * QUADS;
        uint4 rc = __ldg((const uint4*)g_RC[g] + j);
        const unsigned pk[4] = {rc.x, rc.y, rc.z, rc.w};
        unsigned any = 0;
#pragma unroll
        for (int i = 0; i < 4; i++) {
            unsigned rr = pk[i] & 0xffffu;
            any |= (sbm[rr >> 5] >> (rr & 31)) & 1u ? (1u << i) : 0u;
        }
        if (!any) continue;
        float4 v = __ldg((const float4*)(evals + (size_t)g * N_EDGES) + j);
        const float vv[4] = {v.x, v.y, v.z, v.w};
        float4* dst = g ? g_CL3b : g_CL3a;
#pragma unroll
        for (int i = 0; i < 4; i++)
            if (any & (1u << i)) {
                float4 qv = __ldg(g_CL2 + (pk[i] & 0xffffu));
                float p0 = qv.x;                 // R3 parent
                float p1 = g ? qv.z : qv.y;      // R4 / R5 parent
                float p2 = qv.w;                 // R6 parent
                if ((p0 != 0.f) | (p1 != 0.f) | (p2 != 0.f)) {
                    // CL3 slot order {fromR3, fromR6, fromR5/4}
                    red4((float*)&dst[pk[i] >> 16], vv[i] * p0, vv[i] * p2, vv[i] * p1, 0.f);
                }
            }
    }
    barrier_wait(NB);

    // ---- P4: lvl4 (dense; RC stream, float2 gathers of CL3.xy) ----
    for (int q = gtid; q < 2 * QUADS; q += NTHR) {
        int g = q >= QUADS;
        int j = q - g * QUADS;
        const float2* src = (const float2*)(g ? g_CL3b : g_CL3a);
        uint4 rc = __ldg((const uint4*)g_RC[g] + j);
        float4 v = __ldg((const float4*)(evals + (size_t)g * N_EDGES) + j);
        float* base = (float*)g_CL4 + 2 * g;
        {
            float2 q0 = __ldg(src + 2 * (rc.x & 0xffffu));
            float2 q1 = __ldg(src + 2 * (rc.y & 0xffffu));
            if ((q0.x != 0.f) | (q0.y != 0.f)) red2(base + (rc.x >> 16) * 4, v.x * q0.x, v.x * q0.y);
            if ((q1.x != 0.f) | (q1.y != 0.f)) red2(base + (rc.y >> 16) * 4, v.y * q1.x, v.y * q1.y);
        }
        {
            float2 q2 = __ldg(src + 2 * (rc.z & 0xffffu));
            float2 q3 = __ldg(src + 2 * (rc.w & 0xffffu));
            if ((q2.x != 0.f) | (q2.y != 0.f)) red2(base + (rc.z >> 16) * 4, v.z * q2.x, v.z * q2.y);
            if ((q3.x != 0.f) | (q3.y != 0.f)) red2(base + (rc.w >> 16) * 4, v.w * q3.x, v.w * q3.y);
        }
    }
    barrier_wait(NB);

    // ---- P5: dot (all 16 slots) + sigma + zero CL arrays and bitmaps ----
    {
        int n0 = blk * DC;
        int lim = min(DC, N_NODES - n0);
        if (tid < lim) {
            int gn = n0 + tid;
            float2 a = __ldg(g_CL1 + gn);
            float4 c2 = __ldg(g_CL2 + gn);
            float4 c3a = __ldg(g_CL3a + gn);
            float4 c3b = __ldg(g_CL3b + gn);
            float4 c4 = __ldg(g_CL4 + gn);
            pool[0 * DC + tid] = a.x;   pool[1 * DC + tid] = a.y;
            pool[2 * DC + tid] = c2.x;  pool[3 * DC + tid] = c2.y;
            pool[4 * DC + tid] = c2.z;  pool[5 * DC + tid] = c2.w;
            pool[6 * DC + tid] = c3a.x; pool[7 * DC + tid] = c3a.y;
            pool[8 * DC + tid] = c3a.z;
            pool[9 * DC + tid] = c3b.x; pool[10 * DC + tid] = c3b.y;
            pool[11 * DC + tid] = c3b.z;
            pool[12 * DC + tid] = c4.x; pool[13 * DC + tid] = c4.y;
            pool[14 * DC + tid] = c4.z; pool[15 * DC + tid] = c4.w;
            // restore zeros (after the loads; same thread = program order)
            g_CL1[gn] = make_float2(0.f, 0.f);
            g_CL2[gn] = z4; g_CL3a[gn] = z4; g_CL3b[gn] = z4; g_CL4[gn] = z4;
        }
        if (blk == 0 && tid >= 512 && tid < 512 + BM_WORDS) {
            g_bm1[tid - 512] = 0u;
            g_bm2[tid - 512] = 0u;
        }
        __syncthreads();
        if (tid < 128) {  // sigma: sig[1..4] = column sums of slots {0,2,1,5}
            const int slots[4] = {0, 2, 1, 5};
            int vi = tid >> 5, lane = tid & 31;
            float s = 0.f;
            for (int n = lane; n < lim; n += 32) s += pool[slots[vi] * DC + n];
#pragma unroll
            for (int off = 16; off; off >>= 1) s += __shfl_down_sync(0xffffffffu, s, off);
            if (lane == 0) atomicAdd(&g_sig[vi + 1], s);
        }
        int f = tid & 63;
        int bb = (tid >> 6) & 3;
        int vg = tid >> 8;
        float acc0 = 0.f, acc1 = 0.f, acc2 = 0.f, acc3 = 0.f;
        const float* xb = x + ((size_t)bb * N_NODES + n0) * 64 + f;
        const float* rsv = pool + vg * 4 * DC;
        for (int nn = 0; nn < lim; nn++) {
            float xv = __ldg(xb + (size_t)nn * 64);
            acc0 += rsv[0 * DC + nn] * xv;
            acc1 += rsv[1 * DC + nn] * xv;
            acc2 += rsv[2 * DC + nn] * xv;
            acc3 += rsv[3 * DC + nn] * xv;
        }
        atomicAdd(&g_D[c_SVID[vg * 4 + 0]][bb][f], acc0);
        atomicAdd(&g_D[c_SVID[vg * 4 + 1]][bb][f], acc1);
        atomicAdd(&g_D[c_SVID[vg * 4 + 2]][bb][f], acc2);
        atomicAdd(&g_D[c_SVID[vg * 4 + 3]][bb][f], acc3);
    }
    if (blk >= 124) { barrier_arrive(NB); return; }
    barrier_wait(NB);

    // ---- P6a: blocks 0..119 T partials; 120..123 init out = b2 ----
    {
        int lane = tid & 31, w = tid >> 5;
        if (blk < 120) {
            int b = blk & 3, si = (blk >> 2) % 5, pc = blk / 20;
            int e = pc / 3, k = pc % 3;
            int pi = (k == 0) ? 0 : (e * 2 + k);
            int vid = c_VEC_ID[si][pi];
            const float* Dp = vid ? &g_D[vid][b][0] : (x + (size_t)b * N_NODES * 64);
            const float* Wp = W1 + (size_t)pc * 64 * 128;
            if (w < 12) {
                float4 acc = z4;
                for (int f = w; f < 64; f += 12) {
                    float d = __ldg(Dp + f);
                    float4 wv = __ldg((const float4*)(Wp + (size_t)f * 128) + lane);
                    acc.x += d * wv.x; acc.y += d * wv.y;
                    acc.z += d * wv.z; acc.w += d * wv.w;
                }
                part[w][lane] = acc;
            }
            __syncthreads();
            if (w == 0) {
                float4 o = z4;
#pragma unroll
                for (int i = 0; i < 12; i++) {
                    float4 a = part[i][lane];
                    o.x += a.x; o.y += a.y; o.z += a.z; o.w += a.w;
                }
                float* tp = &g_T[si][b][lane * 4];
                atomicAdd(tp + 0, o.x); atomicAdd(tp + 1, o.y);
                atomicAdd(tp + 2, o.z); atomicAdd(tp + 3, o.w);
            }
        } else {
            int b = blk - 120;
            if (tid < 32)
                ((float4*)(out + (size_t)b * 128))[tid] = __ldg((const float4*)b2 + tid);
        }
    }
    if (blk >= 24) { barrier_arrive(124); return; }
    barrier_wait(124);

    // ---- P6b: blocks 0..23 out partials; spare warps zero D ----
    {
        int b = blk & 3, pc = blk >> 2;
        int e = pc / 3, k = pc % 3;
        int si = (k == 0) ? 0 : (e * 2 + k);
        float sg = (si == 0) ? 1.0f : __ldg(&g_sig[si]);
        int lane = tid & 31, w = tid >> 5;
        const float* Tp = &g_T[si][b][0];
        const float* Wp = W2 + (size_t)pc * 128 * 128;
        if (w < 12) {
            float4 acc = z4;
            for (int f = w; f < 128; f += 12) {
                float t = __ldg(Tp + f) + sg * __ldg(b1 + f);
                float4 wv = __ldg((const float4*)(Wp + (size_t)f * 128) + lane);
                acc.x += t * wv.x; acc.y += t * wv.y;
                acc.z += t * wv.z; acc.w += t * wv.w;
            }
            part[w][lane] = acc;
        } else {
            // zero D (not read in P6b): blocks 0..23 x 640 threads cover 4352
            for (int i = blk * 640 + (tid - 384); i < 17 * 4 * 64; i += 24 * 640)
                (&g_D[0][0][0])[i] = 0.f;
        }
        __syncthreads();
        if (w == 0) {
            float4 o = z4;
#pragma unroll
            for (int i = 0; i < 12; i++) {
                float4 a = part[i][lane];
                o.x += a.x; o.y += a.y; o.z += a.z; o.w += a.w;
            }
            float* op = out + (size_t)b * 128 + lane * 4;
            atomicAdd(op + 0, o.x); atomicAdd(op + 1, o.y);
            atomicAdd(op + 2, o.z); atomicAdd(op + 3, o.w);
        }
    }
    barrier_wait(24);
    // zero T and sig (read in P6b, safe only after the 24-block barrier)
    for (int i = blk * NT + tid; i < 5 * 4 * 128; i += 24 * NT) (&g_T[0][0][0])[i] = 0.f;
    if (blk == 0 && tid < 5) g_sig[tid] = 0.f;
}

extern "C" void kernel_launch(void* const* d_in, const int* in_sizes, int n_in,
                              void* d_out, int out_size) {
    const float* x = nullptr;
    const int* eidx = nullptr;
    const float* evals = nullptr;
    const float *W1 = nullptr, *b1 = nullptr, *W2 = nullptr, *b2 = nullptr;
    for (int i = 0; i < n_in; i++) {
        switch (in_sizes[i]) {
            case 2560000: x = (const float*)d_in[i]; break;
            case 1280000: eidx = (const int*)d_in[i]; break;
            case 640000:  evals = (const float*)d_in[i]; break;
            case 49152:   W1 = (const float*)d_in[i]; break;
            case 98304:   W2 = (const float*)d_in[i]; break;
            case 128:
                if (!b1) b1 = (const float*)d_in[i];
                else b2 = (const float*)d_in[i];
                break;
        }
    }
    float* out = (float*)d_out;
    fused_kernel<<<NB, NT>>>(eidx, evals, x, W1, b1, W2, b2, out);
}

// round 11
// speedup vs baseline: 1.5084x; 1.0410x over previous
#include <cuda_runtime.h>

#define N_NODES 10000
#define N_EDGES 320000
#define QUADS (N_EDGES / 4)
#define NB 148
#define NT 1024
#define NTHR (NB * NT)
#define BM_WORDS 320
#define DC 68       // dot chunk: 148 blocks x 68 >= 10000
#define QPB 1082    // quads per block: 148*1082 >= 2*QUADS (last block partial)

// INVARIANT: accumulated scratch (CL*, bm*, D, T, sig) is ZERO at kernel entry
// and restored to ZERO before exit. g_RC is fully overwritten in P1 before any
// read. L1-cached __ldg of data written earlier in this launch is safe: L1 is
// flushed at launch boundaries, global stores/atomics don't allocate in L1,
// and no array is regular-loaded before its producer phase's barrier.
__device__ float2 g_CL1[N_NODES];   // {R1, R2}
__device__ float4 g_CL2[N_NODES];   // {R3, R5, R4, R6}
__device__ float4 g_CL3a[N_NODES];  // {R7, R11, R10, pad}  (lvl4 reads .xy)
__device__ float4 g_CL3b[N_NODES];  // {R8, R12, R9, pad}   (lvl4 reads .xy)
__device__ float4 g_CL4[N_NODES];   // {R13, R15, R14, R16}
__device__ unsigned g_RC[2][N_EDGES];  // packed (row | col<<16) per GSO
__device__ unsigned g_bm1[BM_WORDS];
__device__ unsigned g_bm2[BM_WORDS];
__device__ float g_D[17][4][64];
__device__ float g_T[5][4][128];
__device__ float g_sig[5];
__device__ int g_count;             // returns to 0 at each barrier
__device__ volatile int g_gen;      // monotonic; equality-compare only

__constant__ int c_VEC_ID[5][5] = {
    {0, 1, 3, 2, 6},
    {1, 3, 7, 4, 9},
    {3, 7, 13, 8, 14},
    {2, 5, 10, 6, 12},
    {6, 11, 15, 12, 16}};
// pool slots: CL1.xy, CL2.xyzw, CL3a.xyz, CL3b.xyz  (CL3 slot order {R7,R11,R10}/{R8,R12,R9})
__constant__ int c_SVID[16] = {1, 2, 3, 5, 4, 6, 7, 11, 10, 8, 12, 9, 13, 15, 14, 16};

__device__ __forceinline__ void red2(float* p, float a, float b) {
    asm volatile("red.global.add.v2.f32 [%0], {%1,%2};" :: "l"(p), "f"(a), "f"(b) : "memory");
}
__device__ __forceinline__ void red4(float* p, float a, float b, float c, float d) {
    asm volatile("red.global.add.v4.f32 [%0], {%1,%2,%3,%4};"
                 :: "l"(p), "f"(a), "f"(b), "f"(c), "f"(d) : "memory");
}

__device__ __forceinline__ void barrier_arrive(int target) {
    __syncthreads();
    if (threadIdx.x == 0) {
        __threadfence();
        int gen = g_gen;
        if (atomicAdd(&g_count, 1) == target - 1) {
            g_count = 0;
            __threadfence();
            g_gen = gen + 1;
        }
    }
}
__device__ __forceinline__ void barrier_wait(int target) {
    __syncthreads();
    if (threadIdx.x == 0) {
        __threadfence();
        int gen = g_gen;
        if (atomicAdd(&g_count, 1) == target - 1) {
            g_count = 0;
            __threadfence();
            g_gen = gen + 1;
        } else {
            while (g_gen == gen) __nanosleep(64);
        }
    }
    __syncthreads();
}

__global__ void __launch_bounds__(NT, 1)
fused_kernel(const int* __restrict__ eidx, const float* __restrict__ evals,
             const float* __restrict__ x,
             const float* __restrict__ W1, const float* __restrict__ b1,
             const float* __restrict__ W2, const float* __restrict__ b2,
             float* __restrict__ out) {
    __shared__ __align__(16) float pool[1920];
    __shared__ unsigned sbm[BM_WORDS];
    float4 (*part)[32] = reinterpret_cast<float4(*)[32]>(pool);

    const int tid = threadIdx.x;
    const int blk = blockIdx.x;
    const float4 z4 = make_float4(0.f, 0.f, 0.f, 0.f);

    // Balanced contiguous quad range for this block (all scan phases).
    const int qstart = blk * QPB;
    const int qcount = min(QPB, 2 * QUADS - qstart);

    // ---- P1: lvl1 (parent = e_0) + build bm1 + pack RC = row | col<<16 ----
    for (int t = tid; t < qcount; t += NT) {
        int q = qstart + t;
        int g = q >= QUADS;
        int j = q - g * QUADS;
        const int* eb = eidx + (size_t)g * 2 * N_EDGES;
        int4 r = __ldg((const int4*)eb + j);
        int4 c = __ldg((const int4*)(eb + N_EDGES) + j);
        uint4 p;
        p.x = (unsigned)r.x | ((unsigned)c.x << 16);
        p.y = (unsigned)r.y | ((unsigned)c.y << 16);
        p.z = (unsigned)r.z | ((unsigned)c.z << 16);
        p.w = (unsigned)r.w | ((unsigned)c.w << 16);
        ((uint4*)g_RC[g])[j] = p;
        if (r.x == 0 || r.y == 0 || r.z == 0 || r.w == 0) {
            const int ri[4] = {r.x, r.y, r.z, r.w};
            const int ci[4] = {c.x, c.y, c.z, c.w};
            float* base = (float*)g_CL1 + g;
#pragma unroll
            for (int i = 0; i < 4; i++)
                if (ri[i] == 0) {
                    float v = __ldg(evals + (size_t)g * N_EDGES + j * 4 + i);
                    atomicAdd(base + ci[i] * 2, v);
                    atomicOr(&g_bm1[ci[i] >> 5], 1u << (ci[i] & 31));
                }
        }
    }
    barrier_wait(NB);

    // ---- P2: lvl2 (bm1-filtered; RC stream) + build bm2 ----
    if (tid < BM_WORDS) sbm[tid] = __ldg(&g_bm1[tid]);
    __syncthreads();
    for (int t = tid; t < qcount; t += NT) {
        int q = qstart + t;
        int g = q >= QUADS;
        int j = q - g * QUADS;
        uint4 rc = __ldg((const uint4*)g_RC[g] + j);
        const unsigned pk[4] = {rc.x, rc.y, rc.z, rc.w};
        unsigned any = 0;
#pragma unroll
        for (int i = 0; i < 4; i++) {
            unsigned rr = pk[i] & 0xffffu;
            any |= (sbm[rr >> 5] >> (rr & 31)) & 1u ? (1u << i) : 0u;
        }
        if (!any) continue;
        float* base = (float*)g_CL2 + 2 * g;
#pragma unroll
        for (int i = 0; i < 4; i++)
            if (any & (1u << i)) {
                float2 qv = __ldg(g_CL1 + (pk[i] & 0xffffu));
                if ((qv.x != 0.f) | (qv.y != 0.f)) {
                    unsigned cc = pk[i] >> 16;
                    float v = __ldg(evals + (size_t)g * N_EDGES + j * 4 + i);
                    red2(base + cc * 4, v * qv.x, v * qv.y);
                    atomicOr(&g_bm2[cc >> 5], 1u << (cc & 31));
                }
            }
    }
    barrier_wait(NB);

    // ---- P3: lvl3 (bm2-filtered; RC stream, vector vals) ----
    if (tid < BM_WORDS) sbm[tid] = __ldg(&g_bm2[tid]);
    __syncthreads();
    for (int t = tid; t < qcount; t += NT) {
        int q = qstart + t;
        int g = q >= QUADS;
        int j = q - g * QUADS;
        uint4 rc = __ldg((const uint4*)g_RC[g] + j);
        const unsigned pk[4] = {rc.x, rc.y, rc.z, rc.w};
        unsigned any = 0;
#pragma unroll
        for (int i = 0; i < 4; i++) {
            unsigned rr = pk[i] & 0xffffu;
            any |= (sbm[rr >> 5] >> (rr & 31)) & 1u ? (1u << i) : 0u;
        }
        if (!any) continue;
        float4 v = __ldg((const float4*)(evals + (size_t)g * N_EDGES) + j);
        const float vv[4] = {v.x, v.y, v.z, v.w};
        float4* dst = g ? g_CL3b : g_CL3a;
#pragma unroll
        for (int i = 0; i < 4; i++)
            if (any & (1u << i)) {
                float4 qv = __ldg(g_CL2 + (pk[i] & 0xffffu));
                float p0 = qv.x;                 // R3 parent
                float p1 = g ? qv.z : qv.y;      // R4 / R5 parent
                float p2 = qv.w;                 // R6 parent
                if ((p0 != 0.f) | (p1 != 0.f) | (p2 != 0.f)) {
                    // CL3 slot order {fromR3, fromR6, fromR5/4}
                    red4((float*)&dst[pk[i] >> 16], vv[i] * p0, vv[i] * p2, vv[i] * p1, 0.f);
                }
            }
    }
    barrier_wait(NB);

    // ---- P4: lvl4 (dense; RC stream, float2 gathers of CL3.xy) ----
    for (int t = tid; t < qcount; t += NT) {
        int q = qstart + t;
        int g = q >= QUADS;
        int j = q - g * QUADS;
        const float2* src = (const float2*)(g ? g_CL3b : g_CL3a);
        uint4 rc = __ldg((const uint4*)g_RC[g] + j);
        float4 v = __ldg((const float4*)(evals + (size_t)g * N_EDGES) + j);
        float* base = (float*)g_CL4 + 2 * g;
        {
            float2 q0 = __ldg(src + 2 * (rc.x & 0xffffu));
            float2 q1 = __ldg(src + 2 * (rc.y & 0xffffu));
            if ((q0.x != 0.f) | (q0.y != 0.f)) red2(base + (rc.x >> 16) * 4, v.x * q0.x, v.x * q0.y);
            if ((q1.x != 0.f) | (q1.y != 0.f)) red2(base + (rc.y >> 16) * 4, v.y * q1.x, v.y * q1.y);
        }
        {
            float2 q2 = __ldg(src + 2 * (rc.z & 0xffffu));
            float2 q3 = __ldg(src + 2 * (rc.w & 0xffffu));
            if ((q2.x != 0.f) | (q2.y != 0.f)) red2(base + (rc.z >> 16) * 4, v.z * q2.x, v.z * q2.y);
            if ((q3.x != 0.f) | (q3.y != 0.f)) red2(base + (rc.w >> 16) * 4, v.w * q3.x, v.w * q3.y);
        }
    }
    barrier_wait(NB);

    // ---- P5: dot (all 16 slots) + sigma + zero CL arrays and bitmaps ----
    {
        int n0 = blk * DC;
        int lim = min(DC, N_NODES - n0);
        if (tid < lim) {
            int gn = n0 + tid;
            float2 a = __ldg(g_CL1 + gn);
            float4 c2 = __ldg(g_CL2 + gn);
            float4 c3a = __ldg(g_CL3a + gn);
            float4 c3b = __ldg(g_CL3b + gn);
            float4 c4 = __ldg(g_CL4 + gn);
            pool[0 * DC + tid] = a.x;   pool[1 * DC + tid] = a.y;
            pool[2 * DC + tid] = c2.x;  pool[3 * DC + tid] = c2.y;
            pool[4 * DC + tid] = c2.z;  pool[5 * DC + tid] = c2.w;
            pool[6 * DC + tid] = c3a.x; pool[7 * DC + tid] = c3a.y;
            pool[8 * DC + tid] = c3a.z;
            pool[9 * DC + tid] = c3b.x; pool[10 * DC + tid] = c3b.y;
            pool[11 * DC + tid] = c3b.z;
            pool[12 * DC + tid] = c4.x; pool[13 * DC + tid] = c4.y;
            pool[14 * DC + tid] = c4.z; pool[15 * DC + tid] = c4.w;
            // restore zeros (after the loads; same thread = program order)
            g_CL1[gn] = make_float2(0.f, 0.f);
            g_CL2[gn] = z4; g_CL3a[gn] = z4; g_CL3b[gn] = z4; g_CL4[gn] = z4;
        }
        if (blk == 0 && tid >= 512 && tid < 512 + BM_WORDS) {
            g_bm1[tid - 512] = 0u;
            g_bm2[tid - 512] = 0u;
        }
        __syncthreads();
        if (tid < 128) {  // sigma: sig[1..4] = column sums of slots {0,2,1,5}
            const int slots[4] = {0, 2, 1, 5};
            int vi = tid >> 5, lane = tid & 31;
            float s = 0.f;
            for (int n = lane; n < lim; n += 32) s += pool[slots[vi] * DC + n];
#pragma unroll
            for (int off = 16; off; off >>= 1) s += __shfl_down_sync(0xffffffffu, s, off);
            if (lane == 0) atomicAdd(&g_sig[vi + 1], s);
        }
        int f = tid & 63;
        int bb = (tid >> 6) & 3;
        int vg = tid >> 8;
        float acc0 = 0.f, acc1 = 0.f, acc2 = 0.f, acc3 = 0.f;
        const float* xb = x + ((size_t)bb * N_NODES + n0) * 64 + f;
        const float* rsv = pool + vg * 4 * DC;
        for (int nn = 0; nn < lim; nn++) {
            float xv = __ldg(xb + (size_t)nn * 64);
            acc0 += rsv[0 * DC + nn] * xv;
            acc1 += rsv[1 * DC + nn] * xv;
            acc2 += rsv[2 * DC + nn] * xv;
            acc3 += rsv[3 * DC + nn] * xv;
        }
        atomicAdd(&g_D[c_SVID[vg * 4 + 0]][bb][f], acc0);
        atomicAdd(&g_D[c_SVID[vg * 4 + 1]][bb][f], acc1);
        atomicAdd(&g_D[c_SVID[vg * 4 + 2]][bb][f], acc2);
        atomicAdd(&g_D[c_SVID[vg * 4 + 3]][bb][f], acc3);
    }
    if (blk >= 124) { barrier_arrive(NB); return; }
    barrier_wait(NB);

    // ---- P6a: blocks 0..119 T partials; 120..123 init out = b2 ----
    {
        int lane = tid & 31, w = tid >> 5;
        if (blk < 120) {
            int b = blk & 3, si = (blk >> 2) % 5, pc = blk / 20;
            int e = pc / 3, k = pc % 3;
            int pi = (k == 0) ? 0 : (e * 2 + k);
            int vid = c_VEC_ID[si][pi];
            const float* Dp = vid ? &g_D[vid][b][0] : (x + (size_t)b * N_NODES * 64);
            const float* Wp = W1 + (size_t)pc * 64 * 128;
            if (w < 12) {
                float4 acc = z4;
                for (int f = w; f < 64; f += 12) {
                    float d = __ldg(Dp + f);
                    float4 wv = __ldg((const float4*)(Wp + (size_t)f * 128) + lane);
                    acc.x += d * wv.x; acc.y += d * wv.y;
                    acc.z += d * wv.z; acc.w += d * wv.w;
                }
                part[w][lane] = acc;
            }
            __syncthreads();
            if (w == 0) {
                float4 o = z4;
#pragma unroll
                for (int i = 0; i < 12; i++) {
                    float4 a = part[i][lane];
                    o.x += a.x; o.y += a.y; o.z += a.z; o.w += a.w;
                }
                float* tp = &g_T[si][b][lane * 4];
                atomicAdd(tp + 0, o.x); atomicAdd(tp + 1, o.y);
                atomicAdd(tp + 2, o.z); atomicAdd(tp + 3, o.w);
            }
        } else {
            int b = blk - 120;
            if (tid < 32)
                ((float4*)(out + (size_t)b * 128))[tid] = __ldg((const float4*)b2 + tid);
        }
    }
    if (blk >= 24) { barrier_arrive(124); return; }
    barrier_wait(124);

    // ---- P6b: blocks 0..23 out partials; spare warps zero D ----
    {
        int b = blk & 3, pc = blk >> 2;
        int e = pc / 3, k = pc % 3;
        int si = (k == 0) ? 0 : (e * 2 + k);
        float sg = (si == 0) ? 1.0f : __ldg(&g_sig[si]);
        int lane = tid & 31, w = tid >> 5;
        const float* Tp = &g_T[si][b][0];
        const float* Wp = W2 + (size_t)pc * 128 * 128;
        if (w < 12) {
            float4 acc = z4;
            for (int f = w; f < 128; f += 12) {
                float t = __ldg(Tp + f) + sg * __ldg(b1 + f);
                float4 wv = __ldg((const float4*)(Wp + (size_t)f * 128) + lane);
                acc.x += t * wv.x; acc.y += t * wv.y;
                acc.z += t * wv.z; acc.w += t * wv.w;
            }
            part[w][lane] = acc;
        } else {
            // zero D (not read in P6b): blocks 0..23 x 640 threads cover 4352
            for (int i = blk * 640 + (tid - 384); i < 17 * 4 * 64; i += 24 * 640)
                (&g_D[0][0][0])[i] = 0.f;
        }
        __syncthreads();
        if (w == 0) {
            float4 o = z4;
#pragma unroll
            for (int i = 0; i < 12; i++) {
                float4 a = part[i][lane];
                o.x += a.x; o.y += a.y; o.z += a.z; o.w += a.w;
            }
            float* op = out + (size_t)b * 128 + lane * 4;
            atomicAdd(op + 0, o.x); atomicAdd(op + 1, o.y);
            atomicAdd(op + 2, o.z); atomicAdd(op + 3, o.w);
        }
    }
    barrier_wait(24);
    // zero T and sig (read in P6b, safe only after the 24-block barrier)
    for (int i = blk * NT + tid; i < 5 * 4 * 128; i += 24 * NT) (&g_T[0][0][0])[i] = 0.f;
    if (blk == 0 && tid < 5) g_sig[tid] = 0.f;
}

extern "C" void kernel_launch(void* const* d_in, const int* in_sizes, int n_in,
                              void* d_out, int out_size) {
    const float* x = nullptr;
    const int* eidx = nullptr;
    const float* evals = nullptr;
    const float *W1 = nullptr, *b1 = nullptr, *W2 = nullptr, *b2 = nullptr;
    for (int i = 0; i < n_in; i++) {
        switch (in_sizes[i]) {
            case 2560000: x = (const float*)d_in[i]; break;
            case 1280000: eidx = (const int*)d_in[i]; break;
            case 640000:  evals = (const float*)d_in[i]; break;
            case 49152:   W1 = (const float*)d_in[i]; break;
            case 98304:   W2 = (const float*)d_in[i]; break;
            case 128:
                if (!b1) b1 = (const float*)d_in[i];
                else b2 = (const float*)d_in[i];
                break;
        }
    }
    float* out = (float*)d_out;
    fused_kernel<<<NB, NT>>>(eidx, evals, x, W1, b1, W2, b2, out);
}

// round 12
// speedup vs baseline: 1.5480x; 1.0263x over previous
#include <cuda_runtime.h>

#define N_NODES 10000
#define N_EDGES 320000
#define QUADS (N_EDGES / 4)
#define NB 148
#define NT 1024
#define NTHR (NB * NT)
#define BM_WORDS 320
#define DC 68       // dot chunk: 148 blocks x 68 >= 10000
#define QPB 1082    // quads per block: 148*1082 >= 2*QUADS (last block partial)

// INVARIANT: accumulated scratch (CL*, bm*, D, sig) is ZERO at kernel entry
// and restored to ZERO before exit. g_RC is fully overwritten in P1 before any
// read. L1-cached __ldg of data written earlier in this launch is safe: L1 is
// flushed at launch boundaries, global stores/atomics don't allocate in L1,
// and no array is regular-loaded before its producer phase's barrier.
__device__ float2 g_CL1[N_NODES];   // {R1, R2}
__device__ float4 g_CL2[N_NODES];   // {R3, R5, R4, R6}
__device__ float4 g_CL3a[N_NODES];  // {R7, R11, R10, pad}  (lvl4 reads .xy)
__device__ float4 g_CL3b[N_NODES];  // {R8, R12, R9, pad}   (lvl4 reads .xy)
__device__ float4 g_CL4[N_NODES];   // {R13, R15, R14, R16}
__device__ unsigned g_RC[2][N_EDGES];  // packed (row | col<<16) per GSO
__device__ unsigned g_bm1[BM_WORDS];
__device__ unsigned g_bm2[BM_WORDS];
__device__ float g_D[17][4][64];
__device__ float g_sig[5];
__device__ int g_count;             // returns to 0 at each barrier
__device__ volatile int g_gen;      // monotonic; equality-compare only

__constant__ int c_VEC_ID[5][5] = {
    {0, 1, 3, 2, 6},
    {1, 3, 7, 4, 9},
    {3, 7, 13, 8, 14},
    {2, 5, 10, 6, 12},
    {6, 11, 15, 12, 16}};
// pool slots: CL1.xy, CL2.xyzw, CL3a.xyz, CL3b.xyz, CL4.xyzw
__constant__ int c_SVID[16] = {1, 2, 3, 5, 4, 6, 7, 11, 10, 8, 12, 9, 13, 15, 14, 16};

__device__ __forceinline__ void red2(float* p, float a, float b) {
    asm volatile("red.global.add.v2.f32 [%0], {%1,%2};" :: "l"(p), "f"(a), "f"(b) : "memory");
}
__device__ __forceinline__ void red4(float* p, float a, float b, float c, float d) {
    asm volatile("red.global.add.v4.f32 [%0], {%1,%2,%3,%4};"
                 :: "l"(p), "f"(a), "f"(b), "f"(c), "f"(d) : "memory");
}

__device__ __forceinline__ void barrier_arrive(int target) {
    __syncthreads();
    if (threadIdx.x == 0) {
        __threadfence();
        int gen = g_gen;
        if (atomicAdd(&g_count, 1) == target - 1) {
            g_count = 0;
            __threadfence();
            g_gen = gen + 1;
        }
    }
}
__device__ __forceinline__ void barrier_wait(int target) {
    __syncthreads();
    if (threadIdx.x == 0) {
        __threadfence();
        int gen = g_gen;
        if (atomicAdd(&g_count, 1) == target - 1) {
            g_count = 0;
            __threadfence();
            g_gen = gen + 1;
        } else {
            while (g_gen == gen) { }
        }
    }
    __syncthreads();
}

__global__ void __launch_bounds__(NT, 1)
fused_kernel(const int* __restrict__ eidx, const float* __restrict__ evals,
             const float* __restrict__ x,
             const float* __restrict__ W1, const float* __restrict__ b1,
             const float* __restrict__ W2, const float* __restrict__ b2,
             float* __restrict__ out) {
    __shared__ __align__(16) float pool[1920];
    __shared__ unsigned sbm[BM_WORDS];

    const int tid = threadIdx.x;
    const int blk = blockIdx.x;
    const float4 z4 = make_float4(0.f, 0.f, 0.f, 0.f);

    // Balanced contiguous quad range for this block (all scan phases).
    const int qstart = blk * QPB;
    const int qcount = min(QPB, 2 * QUADS - qstart);

    // ---- P1: lvl1 (parent = e_0) + build bm1 + pack RC; block 0 inits out=b2 ----
    if (blk == 0 && tid < 512)
        out[tid] = __ldg(b2 + (tid & 127));
    for (int t = tid; t < qcount; t += NT) {
        int q = qstart + t;
        int g = q >= QUADS;
        int j = q - g * QUADS;
        const int* eb = eidx + (size_t)g * 2 * N_EDGES;
        int4 r = __ldg((const int4*)eb + j);
        int4 c = __ldg((const int4*)(eb + N_EDGES) + j);
        uint4 p;
        p.x = (unsigned)r.x | ((unsigned)c.x << 16);
        p.y = (unsigned)r.y | ((unsigned)c.y << 16);
        p.z = (unsigned)r.z | ((unsigned)c.z << 16);
        p.w = (unsigned)r.w | ((unsigned)c.w << 16);
        ((uint4*)g_RC[g])[j] = p;
        if (r.x == 0 || r.y == 0 || r.z == 0 || r.w == 0) {
            const int ri[4] = {r.x, r.y, r.z, r.w};
            const int ci[4] = {c.x, c.y, c.z, c.w};
            float* base = (float*)g_CL1 + g;
#pragma unroll
            for (int i = 0; i < 4; i++)
                if (ri[i] == 0) {
                    float v = __ldg(evals + (size_t)g * N_EDGES + j * 4 + i);
                    atomicAdd(base + ci[i] * 2, v);
                    atomicOr(&g_bm1[ci[i] >> 5], 1u << (ci[i] & 31));
                }
        }
    }
    barrier_wait(NB);

    // ---- P2: lvl2 (bm1-filtered; RC stream) + build bm2 ----
    if (tid < BM_WORDS) sbm[tid] = __ldg(&g_bm1[tid]);
    __syncthreads();
    for (int t = tid; t < qcount; t += NT) {
        int q = qstart + t;
        int g = q >= QUADS;
        int j = q - g * QUADS;
        uint4 rc = __ldg((const uint4*)g_RC[g] + j);
        const unsigned pk[4] = {rc.x, rc.y, rc.z, rc.w};
        unsigned any = 0;
#pragma unroll
        for (int i = 0; i < 4; i++) {
            unsigned rr = pk[i] & 0xffffu;
            any |= (sbm[rr >> 5] >> (rr & 31)) & 1u ? (1u << i) : 0u;
        }
        if (!any) continue;
        float* base = (float*)g_CL2 + 2 * g;
#pragma unroll
        for (int i = 0; i < 4; i++)
            if (any & (1u << i)) {
                float2 qv = __ldg(g_CL1 + (pk[i] & 0xffffu));
                if ((qv.x != 0.f) | (qv.y != 0.f)) {
                    unsigned cc = pk[i] >> 16;
                    float v = __ldg(evals + (size_t)g * N_EDGES + j * 4 + i);
                    red2(base + cc * 4, v * qv.x, v * qv.y);
                    atomicOr(&g_bm2[cc >> 5], 1u << (cc & 31));
                }
            }
    }
    barrier_wait(NB);

    // ---- P3: lvl3 (bm2-filtered; RC stream, vector vals) ----
    if (tid < BM_WORDS) sbm[tid] = __ldg(&g_bm2[tid]);
    __syncthreads();
    for (int t = tid; t < qcount; t += NT) {
        int q = qstart + t;
        int g = q >= QUADS;
        int j = q - g * QUADS;
        uint4 rc = __ldg((const uint4*)g_RC[g] + j);
        const unsigned pk[4] = {rc.x, rc.y, rc.z, rc.w};
        unsigned any = 0;
#pragma unroll
        for (int i = 0; i < 4; i++) {
            unsigned rr = pk[i] & 0xffffu;
            any |= (sbm[rr >> 5] >> (rr & 31)) & 1u ? (1u << i) : 0u;
        }
        if (!any) continue;
        float4 v = __ldg((const float4*)(evals + (size_t)g * N_EDGES) + j);
        const float vv[4] = {v.x, v.y, v.z, v.w};
        float4* dst = g ? g_CL3b : g_CL3a;
#pragma unroll
        for (int i = 0; i < 4; i++)
            if (any & (1u << i)) {
                float4 qv = __ldg(g_CL2 + (pk[i] & 0xffffu));
                float p0 = qv.x;                 // R3 parent
                float p1 = g ? qv.z : qv.y;      // R4 / R5 parent
                float p2 = qv.w;                 // R6 parent
                if ((p0 != 0.f) | (p1 != 0.f) | (p2 != 0.f)) {
                    // CL3 slot order {fromR3, fromR6, fromR5/4}
                    red4((float*)&dst[pk[i] >> 16], vv[i] * p0, vv[i] * p2, vv[i] * p1, 0.f);
                }
            }
    }
    barrier_wait(NB);

    // ---- P4: lvl4 scan, then dot of the 12 final slots (CL1..CL3) + sigma
    //          + zero CL1/CL2/bm (per-block node range) ----
    for (int t = tid; t < qcount; t += NT) {
        int q = qstart + t;
        int g = q >= QUADS;
        int j = q - g * QUADS;
        const float2* src = (const float2*)(g ? g_CL3b : g_CL3a);
        uint4 rc = __ldg((const uint4*)g_RC[g] + j);
        float4 v = __ldg((const float4*)(evals + (size_t)g * N_EDGES) + j);
        float* base = (float*)g_CL4 + 2 * g;
        {
            float2 q0 = __ldg(src + 2 * (rc.x & 0xffffu));
            float2 q1 = __ldg(src + 2 * (rc.y & 0xffffu));
            if ((q0.x != 0.f) | (q0.y != 0.f)) red2(base + (rc.x >> 16) * 4, v.x * q0.x, v.x * q0.y);
            if ((q1.x != 0.f) | (q1.y != 0.f)) red2(base + (rc.y >> 16) * 4, v.y * q1.x, v.y * q1.y);
        }
        {
            float2 q2 = __ldg(src + 2 * (rc.z & 0xffffu));
            float2 q3 = __ldg(src + 2 * (rc.w & 0xffffu));
            if ((q2.x != 0.f) | (q2.y != 0.f)) red2(base + (rc.z >> 16) * 4, v.z * q2.x, v.z * q2.y);
            if ((q3.x != 0.f) | (q3.y != 0.f)) red2(base + (rc.w >> 16) * 4, v.w * q3.x, v.w * q3.y);
        }
    }
    {
        int n0 = blk * DC;
        int lim = min(DC, N_NODES - n0);
        if (tid < lim) {
            int gn = n0 + tid;
            float2 a = __ldg(g_CL1 + gn);
            float4 c2 = __ldg(g_CL2 + gn);
            float4 c3a = __ldg(g_CL3a + gn);
            float4 c3b = __ldg(g_CL3b + gn);
            pool[0 * DC + tid] = a.x;   pool[1 * DC + tid] = a.y;
            pool[2 * DC + tid] = c2.x;  pool[3 * DC + tid] = c2.y;
            pool[4 * DC + tid] = c2.z;  pool[5 * DC + tid] = c2.w;
            pool[6 * DC + tid] = c3a.x; pool[7 * DC + tid] = c3a.y;
            pool[8 * DC + tid] = c3a.z;
            pool[9 * DC + tid] = c3b.x; pool[10 * DC + tid] = c3b.y;
            pool[11 * DC + tid] = c3b.z;
            // restore zeros (after loads; same thread = program order);
            // CL1/CL2 are not read by any other block in P4
            g_CL1[gn] = make_float2(0.f, 0.f);
            g_CL2[gn] = z4;
        }
        if (blk == 0 && tid >= 512 && tid < 512 + BM_WORDS) {
            g_bm1[tid - 512] = 0u;
            g_bm2[tid - 512] = 0u;
        }
        __syncthreads();
        if (tid < 128) {  // sigma: sig[1..4] = column sums of slots {0,2,1,5}
            const int slots[4] = {0, 2, 1, 5};
            int vi = tid >> 5, lane = tid & 31;
            float s = 0.f;
            for (int n = lane; n < lim; n += 32) s += pool[slots[vi] * DC + n];
#pragma unroll
            for (int off = 16; off; off >>= 1) s += __shfl_down_sync(0xffffffffu, s, off);
            if (lane == 0) atomicAdd(&g_sig[vi + 1], s);
        }
        int f = tid & 63;
        int bb = (tid >> 6) & 3;
        int vg = tid >> 8;  // 0..3, 3 slots each
        float a0 = 0.f, a1 = 0.f, a2 = 0.f;
        const float* xb = x + ((size_t)bb * N_NODES + n0) * 64 + f;
        const float* rsv = pool + vg * 3 * DC;
        for (int nn = 0; nn < lim; nn++) {
            float xv = __ldg(xb + (size_t)nn * 64);
            a0 += rsv[0 * DC + nn] * xv;
            a1 += rsv[1 * DC + nn] * xv;
            a2 += rsv[2 * DC + nn] * xv;
        }
        atomicAdd(&g_D[c_SVID[vg * 3 + 0]][bb][f], a0);
        atomicAdd(&g_D[c_SVID[vg * 3 + 1]][bb][f], a1);
        atomicAdd(&g_D[c_SVID[vg * 3 + 2]][bb][f], a2);
    }
    barrier_wait(NB);

    // ---- P5: dot of the 4 CL4 slots + zero CL3/CL4 ----
    {
        int n0 = blk * DC;
        int lim = min(DC, N_NODES - n0);
        if (tid < lim) {
            int gn = n0 + tid;
            float4 c4 = __ldg(g_CL4 + gn);
            pool[0 * DC + tid] = c4.x; pool[1 * DC + tid] = c4.y;
            pool[2 * DC + tid] = c4.z; pool[3 * DC + tid] = c4.w;
            g_CL4[gn] = z4;
            g_CL3a[gn] = z4;
            g_CL3b[gn] = z4;
        }
        __syncthreads();
        int f = tid & 63;
        int bb = (tid >> 6) & 3;
        int vg = tid >> 8;  // 0..3, 1 slot each
        float a0 = 0.f;
        const float* xb = x + ((size_t)bb * N_NODES + n0) * 64 + f;
        const float* rsv = pool + vg * DC;
        for (int nn = 0; nn < lim; nn++)
            a0 += rsv[nn] * __ldg(xb + (size_t)nn * 64);
        atomicAdd(&g_D[c_SVID[12 + vg]][bb][f], a0);
    }
    if (blk >= 24) { barrier_arrive(NB); return; }
    barrier_wait(NB);

    // ---- PE: blocks 0..23 = (b, pc2): T[si] in smem, then out += T @ W2[pc2] ----
    {
        int b = blk & 3, pc2 = blk >> 2;
        int e2 = pc2 / 3, k2 = pc2 % 3;
        int si = (k2 == 0) ? 0 : (e2 * 2 + k2);
        float sg = (si == 0) ? 1.0f : __ldg(&g_sig[si]);
        int g = tid & 127, fo = tid >> 7;  // 8 f-groups
        float* Tl = pool + 1024;           // Tl[128]
        // Step 1: partials of T = sum_pc1 D[vid] @ W1[pc1]
        float acc = 0.f;
#pragma unroll
        for (int pc1 = 0; pc1 < 6; pc1++) {
            int e1 = pc1 / 3, k1 = pc1 % 3;
            int pi = (k1 == 0) ? 0 : (e1 * 2 + k1);
            int vid = c_VEC_ID[si][pi];
            const float* Dp = vid ? &g_D[vid][b][0] : (x + (size_t)b * N_NODES * 64);
            const float* Wp = W1 + (size_t)pc1 * 64 * 128;
#pragma unroll
            for (int i = 0; i < 8; i++) {
                int f = fo * 8 + i;
                acc += __ldg(Dp + f) * __ldg(Wp + (size_t)f * 128 + g);
            }
        }
        pool[fo * 128 + g] = acc;
        __syncthreads();
        if (fo == 0) {
            float s = sg * __ldg(b1 + g);
#pragma unroll
            for (int i = 0; i < 8; i++) s += pool[i * 128 + g];
            Tl[g] = s;
        }
        __syncthreads();
        // Step 2: out[b] += Tl @ W2[pc2]
        const float* Wp2 = W2 + (size_t)pc2 * 128 * 128;
        float acc2 = 0.f;
#pragma unroll
        for (int i = 0; i < 16; i++) {
            int f = fo * 16 + i;
            acc2 += Tl[f] * __ldg(Wp2 + (size_t)f * 128 + g);
        }
        __syncthreads();
        pool[fo * 128 + g] = acc2;
        __syncthreads();
        if (fo == 0) {
            float s = 0.f;
#pragma unroll
            for (int i = 0; i < 8; i++) s += pool[i * 128 + g];
            atomicAdd(out + (size_t)b * 128 + g, s);
        }
    }
    barrier_wait(24);
    // zero D and sig (read in PE; safe only after the 24-block barrier)
    for (int i = blk * NT + tid; i < 17 * 4 * 64; i += 24 * NT) (&g_D[0][0][0])[i] = 0.f;
    if (blk == 0 && tid < 5) g_sig[tid] = 0.f;
}

extern "C" void kernel_launch(void* const* d_in, const int* in_sizes, int n_in,
                              void* d_out, int out_size) {
    const float* x = nullptr;
    const int* eidx = nullptr;
    const float* evals = nullptr;
    const float *W1 = nullptr, *b1 = nullptr, *W2 = nullptr, *b2 = nullptr;
    for (int i = 0; i < n_in; i++) {
        switch (in_sizes[i]) {
            case 2560000: x = (const float*)d_in[i]; break;
            case 1280000: eidx = (const int*)d_in[i]; break;
            case 640000:  evals = (const float*)d_in[i]; break;
            case 49152:   W1 = (const float*)d_in[i]; break;
            case 98304:   W2 = (const float*)d_in[i]; break;
            case 128:
                if (!b1) b1 = (const float*)d_in[i];
                else b2 = (const float*)d_in[i];
                break;
        }
    }
    float* out = (float*)d_out;
    fused_kernel<<<NB, NT>>>(eidx, evals, x, W1, b1, W2, b2, out);
}

// round 13
// speedup vs baseline: 1.5910x; 1.0278x over previous
#include <cuda_runtime.h>

#define N_NODES 10000
#define N_EDGES 320000
#define QUADS (N_EDGES / 4)
#define NB 148
#define NT 1024
#define NTHR (NB * NT)
#define BM_WORDS 320
#define DC 68       // dot chunk: 148 blocks x 68 >= 10000
#define QPB 1082    // quads per block: 148*1082 >= 2*QUADS (last block partial)

// INVARIANT: accumulated scratch (CL*, bm*, D, sig) is ZERO at kernel entry
// and restored to ZERO before exit. g_RC is fully overwritten in P1 before any
// read. L1-cached __ldg of data written earlier in this launch is safe: L1 is
// flushed at launch boundaries, global stores/atomics don't allocate in L1,
// and no array is regular-loaded before its producer phase's barrier.
__device__ float2 g_CL1[N_NODES];   // {R1, R2}
__device__ float4 g_CL2[N_NODES];   // {R3, R5, R4, R6}
__device__ float4 g_CL3a[N_NODES];  // {R7, R11, R10, pad}  (lvl4 reads .xy)
__device__ float4 g_CL3b[N_NODES];  // {R8, R12, R9, pad}   (lvl4 reads .xy)
__device__ float4 g_CL4[N_NODES];   // {R13, R15, R14, R16}
__device__ unsigned g_RC[2][N_EDGES];  // packed (row | col<<16) per GSO
__device__ unsigned g_bm1[BM_WORDS];
__device__ unsigned g_bm2[BM_WORDS];
__device__ float g_D[17][4][64];
__device__ float g_sig[5];
__device__ int g_count;             // returns to 0 at each barrier
__device__ volatile int g_gen;      // monotonic; equality-compare only

__constant__ int c_VEC_ID[5][5] = {
    {0, 1, 3, 2, 6},
    {1, 3, 7, 4, 9},
    {3, 7, 13, 8, 14},
    {2, 5, 10, 6, 12},
    {6, 11, 15, 12, 16}};
// pool slots: CL1.xy, CL2.xyzw, CL3a.xyz, CL3b.xyz, CL4.xyzw
__constant__ int c_SVID[16] = {1, 2, 3, 5, 4, 6, 7, 11, 10, 8, 12, 9, 13, 15, 14, 16};

__device__ __forceinline__ void red2(float* p, float a, float b) {
    asm volatile("red.global.add.v2.f32 [%0], {%1,%2};" :: "l"(p), "f"(a), "f"(b) : "memory");
}
__device__ __forceinline__ void red4(float* p, float a, float b, float c, float d) {
    asm volatile("red.global.add.v4.f32 [%0], {%1,%2,%3,%4};"
                 :: "l"(p), "f"(a), "f"(b), "f"(c), "f"(d) : "memory");
}

__device__ __forceinline__ void barrier_arrive(int target) {
    __syncthreads();
    if (threadIdx.x == 0) {
        __threadfence();
        int gen = g_gen;
        if (atomicAdd(&g_count, 1) == target - 1) {
            g_count = 0;
            __threadfence();
            g_gen = gen + 1;
        }
    }
}
__device__ __forceinline__ void barrier_wait(int target) {
    __syncthreads();
    if (threadIdx.x == 0) {
        __threadfence();
        int gen = g_gen;
        if (atomicAdd(&g_count, 1) == target - 1) {
            g_count = 0;
            __threadfence();
            g_gen = gen + 1;
        } else {
            while (g_gen == gen) { }
        }
    }
    __syncthreads();
}

__global__ void __launch_bounds__(NT, 1)
fused_kernel(const int* __restrict__ eidx, const float* __restrict__ evals,
             const float* __restrict__ x,
             const float* __restrict__ W1, const float* __restrict__ b1,
             const float* __restrict__ W2, const float* __restrict__ b2,
             float* __restrict__ out) {
    __shared__ __align__(16) float pool[1920];
    __shared__ unsigned sbm[BM_WORDS];

    const int tid = threadIdx.x;
    const int blk = blockIdx.x;
    const float4 z4 = make_float4(0.f, 0.f, 0.f, 0.f);

    // Balanced contiguous quad range; each thread owns quads t0=tid, t1=tid+1024.
    const int qstart = blk * QPB;
    const int qcount = min(QPB, 2 * QUADS - qstart);
    const bool h0 = tid < qcount;
    const bool h1 = tid + NT < qcount;
    const int q0 = qstart + tid;
    const int q1 = qstart + tid + NT;
    const int g0 = q0 >= QUADS, j0 = q0 - g0 * QUADS;
    const int g1 = q1 >= QUADS, j1 = q1 - g1 * QUADS;

    // ---- P1: lvl1 (parent = e_0) + build bm1 + pack RC; block 0 inits out=b2 ----
    if (blk == 0 && tid < 512)
        out[tid] = __ldg(b2 + (tid & 127));
    {
        int4 r0, c0, r1, c1;
        if (h0) {
            const int* eb = eidx + (size_t)g0 * 2 * N_EDGES;
            r0 = __ldg((const int4*)eb + j0);
            c0 = __ldg((const int4*)(eb + N_EDGES) + j0);
        }
        if (h1) {
            const int* eb = eidx + (size_t)g1 * 2 * N_EDGES;
            r1 = __ldg((const int4*)eb + j1);
            c1 = __ldg((const int4*)(eb + N_EDGES) + j1);
        }
        if (h0) {
            uint4 p;
            p.x = (unsigned)r0.x | ((unsigned)c0.x << 16);
            p.y = (unsigned)r0.y | ((unsigned)c0.y << 16);
            p.z = (unsigned)r0.z | ((unsigned)c0.z << 16);
            p.w = (unsigned)r0.w | ((unsigned)c0.w << 16);
            ((uint4*)g_RC[g0])[j0] = p;
            if (r0.x == 0 || r0.y == 0 || r0.z == 0 || r0.w == 0) {
                const int ri[4] = {r0.x, r0.y, r0.z, r0.w};
                const int ci[4] = {c0.x, c0.y, c0.z, c0.w};
                float* base = (float*)g_CL1 + g0;
#pragma unroll
                for (int i = 0; i < 4; i++)
                    if (ri[i] == 0) {
                        float v = __ldg(evals + (size_t)g0 * N_EDGES + j0 * 4 + i);
                        atomicAdd(base + ci[i] * 2, v);
                        atomicOr(&g_bm1[ci[i] >> 5], 1u << (ci[i] & 31));
                    }
            }
        }
        if (h1) {
            uint4 p;
            p.x = (unsigned)r1.x | ((unsigned)c1.x << 16);
            p.y = (unsigned)r1.y | ((unsigned)c1.y << 16);
            p.z = (unsigned)r1.z | ((unsigned)c1.z << 16);
            p.w = (unsigned)r1.w | ((unsigned)c1.w << 16);
            ((uint4*)g_RC[g1])[j1] = p;
            if (r1.x == 0 || r1.y == 0 || r1.z == 0 || r1.w == 0) {
                const int ri[4] = {r1.x, r1.y, r1.z, r1.w};
                const int ci[4] = {c1.x, c1.y, c1.z, c1.w};
                float* base = (float*)g_CL1 + g1;
#pragma unroll
                for (int i = 0; i < 4; i++)
                    if (ri[i] == 0) {
                        float v = __ldg(evals + (size_t)g1 * N_EDGES + j1 * 4 + i);
                        atomicAdd(base + ci[i] * 2, v);
                        atomicOr(&g_bm1[ci[i] >> 5], 1u << (ci[i] & 31));
                    }
            }
        }
    }
    barrier_wait(NB);

    // ---- P2: lvl2 (bm1-filtered; RC stream) + build bm2 ----
    if (tid < BM_WORDS) sbm[tid] = __ldg(&g_bm1[tid]);
    __syncthreads();
    {
        uint4 rc0, rc1;
        if (h0) rc0 = __ldg((const uint4*)g_RC[g0] + j0);
        if (h1) rc1 = __ldg((const uint4*)g_RC[g1] + j1);
        unsigned pk0[4] = {rc0.x, rc0.y, rc0.z, rc0.w};
        unsigned pk1[4] = {rc1.x, rc1.y, rc1.z, rc1.w};
        unsigned m0 = 0, m1 = 0;
#pragma unroll
        for (int i = 0; i < 4; i++) {
            unsigned rr = pk0[i] & 0xffffu;
            if (h0) m0 |= (sbm[rr >> 5] >> (rr & 31)) & 1u ? (1u << i) : 0u;
            unsigned ss = pk1[i] & 0xffffu;
            if (h1) m1 |= (sbm[ss >> 5] >> (ss & 31)) & 1u ? (1u << i) : 0u;
        }
        if (m0) {
            float* base = (float*)g_CL2 + 2 * g0;
#pragma unroll
            for (int i = 0; i < 4; i++)
                if (m0 & (1u << i)) {
                    float2 qv = __ldg(g_CL1 + (pk0[i] & 0xffffu));
                    if ((qv.x != 0.f) | (qv.y != 0.f)) {
                        unsigned cc = pk0[i] >> 16;
                        float v = __ldg(evals + (size_t)g0 * N_EDGES + j0 * 4 + i);
                        red2(base + cc * 4, v * qv.x, v * qv.y);
                        atomicOr(&g_bm2[cc >> 5], 1u << (cc & 31));
                    }
                }
        }
        if (m1) {
            float* base = (float*)g_CL2 + 2 * g1;
#pragma unroll
            for (int i = 0; i < 4; i++)
                if (m1 & (1u << i)) {
                    float2 qv = __ldg(g_CL1 + (pk1[i] & 0xffffu));
                    if ((qv.x != 0.f) | (qv.y != 0.f)) {
                        unsigned cc = pk1[i] >> 16;
                        float v = __ldg(evals + (size_t)g1 * N_EDGES + j1 * 4 + i);
                        red2(base + cc * 4, v * qv.x, v * qv.y);
                        atomicOr(&g_bm2[cc >> 5], 1u << (cc & 31));
                    }
                }
        }
    }
    barrier_wait(NB);

    // ---- P3: lvl3 (bm2-filtered; hoisted gathers for both quads) ----
    if (tid < BM_WORDS) sbm[tid] = __ldg(&g_bm2[tid]);
    __syncthreads();
    {
        uint4 rc0, rc1;
        if (h0) rc0 = __ldg((const uint4*)g_RC[g0] + j0);
        if (h1) rc1 = __ldg((const uint4*)g_RC[g1] + j1);
        unsigned pk0[4] = {rc0.x, rc0.y, rc0.z, rc0.w};
        unsigned pk1[4] = {rc1.x, rc1.y, rc1.z, rc1.w};
        unsigned m0 = 0, m1 = 0;
#pragma unroll
        for (int i = 0; i < 4; i++) {
            unsigned rr = pk0[i] & 0xffffu;
            if (h0) m0 |= (sbm[rr >> 5] >> (rr & 31)) & 1u ? (1u << i) : 0u;
            unsigned ss = pk1[i] & 0xffffu;
            if (h1) m1 |= (sbm[ss >> 5] >> (ss & 31)) & 1u ? (1u << i) : 0u;
        }
        if (m0 | m1) {
            float4 v0, v1;
            if (m0) v0 = __ldg((const float4*)(evals + (size_t)g0 * N_EDGES) + j0);
            if (m1) v1 = __ldg((const float4*)(evals + (size_t)g1 * N_EDGES) + j1);
            // hoisted gathers: all 8 issue before any red
            float4 qa[4], qb[4];
#pragma unroll
            for (int i = 0; i < 4; i++)
                qa[i] = (m0 & (1u << i)) ? __ldg(g_CL2 + (pk0[i] & 0xffffu)) : z4;
#pragma unroll
            for (int i = 0; i < 4; i++)
                qb[i] = (m1 & (1u << i)) ? __ldg(g_CL2 + (pk1[i] & 0xffffu)) : z4;
            const float vv0[4] = {v0.x, v0.y, v0.z, v0.w};
            const float vv1[4] = {v1.x, v1.y, v1.z, v1.w};
            float4* dst0 = g0 ? g_CL3b : g_CL3a;
            float4* dst1 = g1 ? g_CL3b : g_CL3a;
#pragma unroll
            for (int i = 0; i < 4; i++)
                if (m0 & (1u << i)) {
                    float p0 = qa[i].x;
                    float p1 = g0 ? qa[i].z : qa[i].y;
                    float p2 = qa[i].w;
                    if ((p0 != 0.f) | (p1 != 0.f) | (p2 != 0.f))
                        red4((float*)&dst0[pk0[i] >> 16], vv0[i] * p0, vv0[i] * p2, vv0[i] * p1, 0.f);
                }
#pragma unroll
            for (int i = 0; i < 4; i++)
                if (m1 & (1u << i)) {
                    float p0 = qb[i].x;
                    float p1 = g1 ? qb[i].z : qb[i].y;
                    float p2 = qb[i].w;
                    if ((p0 != 0.f) | (p1 != 0.f) | (p2 != 0.f))
                        red4((float*)&dst1[pk1[i] >> 16], vv1[i] * p0, vv1[i] * p2, vv1[i] * p1, 0.f);
                }
        }
    }
    barrier_wait(NB);

    // ---- P4: lvl4 (dense; hoisted float2 gathers for both quads), then dot of
    //          the 12 final slots + sigma + zero CL1/CL2/bm ----
    {
        uint4 rc0, rc1;
        float4 v0, v1;
        if (h0) {
            rc0 = __ldg((const uint4*)g_RC[g0] + j0);
            v0 = __ldg((const float4*)(evals + (size_t)g0 * N_EDGES) + j0);
        }
        if (h1) {
            rc1 = __ldg((const uint4*)g_RC[g1] + j1);
            v1 = __ldg((const float4*)(evals + (size_t)g1 * N_EDGES) + j1);
        }
        const float2* s0 = (const float2*)(g0 ? g_CL3b : g_CL3a);
        const float2* s1 = (const float2*)(g1 ? g_CL3b : g_CL3a);
        const unsigned pk0[4] = {rc0.x, rc0.y, rc0.z, rc0.w};
        const unsigned pk1[4] = {rc1.x, rc1.y, rc1.z, rc1.w};
        float2 ga[4], gb[4];
#pragma unroll
        for (int i = 0; i < 4; i++)
            ga[i] = h0 ? __ldg(s0 + 2 * (pk0[i] & 0xffffu)) : make_float2(0.f, 0.f);
#pragma unroll
        for (int i = 0; i < 4; i++)
            gb[i] = h1 ? __ldg(s1 + 2 * (pk1[i] & 0xffffu)) : make_float2(0.f, 0.f);
        const float vv0[4] = {v0.x, v0.y, v0.z, v0.w};
        const float vv1[4] = {v1.x, v1.y, v1.z, v1.w};
        float* base0 = (float*)g_CL4 + 2 * g0;
        float* base1 = (float*)g_CL4 + 2 * g1;
#pragma unroll
        for (int i = 0; i < 4; i++)
            if (((ga[i].x != 0.f) | (ga[i].y != 0.f)) && h0)
                red2(base0 + (pk0[i] >> 16) * 4, vv0[i] * ga[i].x, vv0[i] * ga[i].y);
#pragma unroll
        for (int i = 0; i < 4; i++)
            if (((gb[i].x != 0.f) | (gb[i].y != 0.f)) && h1)
                red2(base1 + (pk1[i] >> 16) * 4, vv1[i] * gb[i].x, vv1[i] * gb[i].y);
    }
    {
        int n0 = blk * DC;
        int lim = min(DC, N_NODES - n0);
        if (tid < lim) {
            int gn = n0 + tid;
            float2 a = __ldg(g_CL1 + gn);
            float4 c2 = __ldg(g_CL2 + gn);
            float4 c3a = __ldg(g_CL3a + gn);
            float4 c3b = __ldg(g_CL3b + gn);
            pool[0 * DC + tid] = a.x;   pool[1 * DC + tid] = a.y;
            pool[2 * DC + tid] = c2.x;  pool[3 * DC + tid] = c2.y;
            pool[4 * DC + tid] = c2.z;  pool[5 * DC + tid] = c2.w;
            pool[6 * DC + tid] = c3a.x; pool[7 * DC + tid] = c3a.y;
            pool[8 * DC + tid] = c3a.z;
            pool[9 * DC + tid] = c3b.x; pool[10 * DC + tid] = c3b.y;
            pool[11 * DC + tid] = c3b.z;
            // restore zeros (after loads; same thread = program order);
            // CL1/CL2 are not read by any other block in P4
            g_CL1[gn] = make_float2(0.f, 0.f);
            g_CL2[gn] = z4;
        }
        if (blk == 0 && tid >= 512 && tid < 512 + BM_WORDS) {
            g_bm1[tid - 512] = 0u;
            g_bm2[tid - 512] = 0u;
        }
        __syncthreads();
        if (tid < 128) {  // sigma: sig[1..4] = column sums of slots {0,2,1,5}
            const int slots[4] = {0, 2, 1, 5};
            int vi = tid >> 5, lane = tid & 31;
            float s = 0.f;
            for (int n = lane; n < lim; n += 32) s += pool[slots[vi] * DC + n];
#pragma unroll
            for (int off = 16; off; off >>= 1) s += __shfl_down_sync(0xffffffffu, s, off);
            if (lane == 0) atomicAdd(&g_sig[vi + 1], s);
        }
        int f = tid & 63;
        int bb = (tid >> 6) & 3;
        int vg = tid >> 8;  // 0..3, 3 slots each
        float a0 = 0.f, a1 = 0.f, a2 = 0.f;
        const float* xb = x + ((size_t)bb * N_NODES + n0) * 64 + f;
        const float* rsv = pool + vg * 3 * DC;
        for (int nn = 0; nn < lim; nn++) {
            float xv = __ldg(xb + (size_t)nn * 64);
            a0 += rsv[0 * DC + nn] * xv;
            a1 += rsv[1 * DC + nn] * xv;
            a2 += rsv[2 * DC + nn] * xv;
        }
        atomicAdd(&g_D[c_SVID[vg * 3 + 0]][bb][f], a0);
        atomicAdd(&g_D[c_SVID[vg * 3 + 1]][bb][f], a1);
        atomicAdd(&g_D[c_SVID[vg * 3 + 2]][bb][f], a2);
    }
    barrier_wait(NB);

    // ---- P5: dot of the 4 CL4 slots + zero CL3/CL4 ----
    {
        int n0 = blk * DC;
        int lim = min(DC, N_NODES - n0);
        if (tid < lim) {
            int gn = n0 + tid;
            float4 c4 = __ldg(g_CL4 + gn);
            pool[0 * DC + tid] = c4.x; pool[1 * DC + tid] = c4.y;
            pool[2 * DC + tid] = c4.z; pool[3 * DC + tid] = c4.w;
            g_CL4[gn] = z4;
            g_CL3a[gn] = z4;
            g_CL3b[gn] = z4;
        }
        __syncthreads();
        int f = tid & 63;
        int bb = (tid >> 6) & 3;
        int vg = tid >> 8;  // 0..3, 1 slot each
        float a0 = 0.f;
        const float* xb = x + ((size_t)bb * N_NODES + n0) * 64 + f;
        const float* rsv = pool + vg * DC;
        for (int nn = 0; nn < lim; nn++)
            a0 += rsv[nn] * __ldg(xb + (size_t)nn * 64);
        atomicAdd(&g_D[c_SVID[12 + vg]][bb][f], a0);
    }
    if (blk >= 24) { barrier_arrive(NB); return; }
    barrier_wait(NB);

    // ---- PE: blocks 0..23 = (b, pc2): T[si] in smem, then out += T @ W2[pc2] ----
    {
        int b = blk & 3, pc2 = blk >> 2;
        int e2 = pc2 / 3, k2 = pc2 % 3;
        int si = (k2 == 0) ? 0 : (e2 * 2 + k2);
        float sg = (si == 0) ? 1.0f : __ldg(&g_sig[si]);
        int g = tid & 127, fo = tid >> 7;  // 8 f-groups
        float* Tl = pool + 1024;           // Tl[128]
        // Step 1: partials of T = sum_pc1 D[vid] @ W1[pc1]
        float acc = 0.f;
#pragma unroll
        for (int pc1 = 0; pc1 < 6; pc1++) {
            int e1 = pc1 / 3, k1 = pc1 % 3;
            int pi = (k1 == 0) ? 0 : (e1 * 2 + k1);
            int vid = c_VEC_ID[si][pi];
            const float* Dp = vid ? &g_D[vid][b][0] : (x + (size_t)b * N_NODES * 64);
            const float* Wp = W1 + (size_t)pc1 * 64 * 128;
#pragma unroll
            for (int i = 0; i < 8; i++) {
                int f = fo * 8 + i;
                acc += __ldg(Dp + f) * __ldg(Wp + (size_t)f * 128 + g);
            }
        }
        pool[fo * 128 + g] = acc;
        __syncthreads();
        if (fo == 0) {
            float s = sg * __ldg(b1 + g);
#pragma unroll
            for (int i = 0; i < 8; i++) s += pool[i * 128 + g];
            Tl[g] = s;
        }
        __syncthreads();
        // Step 2: out[b] += Tl @ W2[pc2]
        const float* Wp2 = W2 + (size_t)pc2 * 128 * 128;
        float acc2 = 0.f;
#pragma unroll
        for (int i = 0; i < 16; i++) {
            int f = fo * 16 + i;
            acc2 += Tl[f] * __ldg(Wp2 + (size_t)f * 128 + g);
        }
        __syncthreads();
        pool[fo * 128 + g] = acc2;
        __syncthreads();
        if (fo == 0) {
            float s = 0.f;
#pragma unroll
            for (int i = 0; i < 8; i++) s += pool[i * 128 + g];
            atomicAdd(out + (size_t)b * 128 + g, s);
        }
    }
    barrier_wait(24);
    // zero D and sig (read in PE; safe only after the 24-block barrier)
    for (int i = blk * NT + tid; i < 17 * 4 * 64; i += 24 * NT) (&g_D[0][0][0])[i] = 0.f;
    if (blk == 0 && tid < 5) g_sig[tid] = 0.f;
}

extern "C" void kernel_launch(void* const* d_in, const int* in_sizes, int n_in,
                              void* d_out, int out_size) {
    const float* x = nullptr;
    const int* eidx = nullptr;
    const float* evals = nullptr;
    const float *W1 = nullptr, *b1 = nullptr, *W2 = nullptr, *b2 = nullptr;
    for (int i = 0; i < n_in; i++) {
        switch (in_sizes[i]) {
            case 2560000: x = (const float*)d_in[i]; break;
            case 1280000: eidx = (const int*)d_in[i]; break;
            case 640000:  evals = (const float*)d_in[i]; break;
            case 49152:   W1 = (const float*)d_in[i]; break;
            case 98304:   W2 = (const float*)d_in[i]; break;
            case 128:
                if (!b1) b1 = (const float*)d_in[i];
                else b2 = (const float*)d_in[i];
                break;
        }
    }
    float* out = (float*)d_out;
    fused_kernel<<<NB, NT>>>(eidx, evals, x, W1, b1, W2, b2, out);
}